// round 3
// baseline (speedup 1.0000x reference)
#include <cuda_runtime.h>
#include <math.h>

#define Nn 50000
#define Ee 640000
#define Dd 128
#define Hh 8
#define DHd 16
#define FFd 256
#define Cc 5
#define Ll 6
#define EPSf 1e-5f

#define SCAN_B 1024
#define SCAN_NB ((Nn + SCAN_B - 1) / SCAN_B)  // 49

// ---------------- scratch (device globals; no allocs allowed) ----------------
__device__ float g_x[Nn * Dd];
__device__ float g_q[Nn * Dd];
__device__ float g_k[Nn * Dd];
__device__ float g_v[Nn * Dd];
__device__ float g_attn[Nn * Dd];
__device__ float g_tmp[Nn * Dd];
__device__ float g_ff[Nn * FFd];
__device__ double g_colsum[Dd];
__device__ double g_colsq[Dd];
// CSR
__device__ int g_deg[Nn];
__device__ int g_cursor[Nn];
__device__ int g_rowptr[Nn + 1];
__device__ int g_scan[Nn];
__device__ int g_bsum[SCAN_NB];
__device__ int g_boff[SCAN_NB];
__device__ int g_col[Ee];

// packed fp32x2 FMA (Blackwell FFMA2, PTX-only)
__device__ __forceinline__ void fma2(unsigned long long& d, unsigned long long a,
                                     unsigned long long b) {
    asm("fma.rn.f32x2 %0, %1, %2, %0;" : "+l"(d) : "l"(a), "l"(b));
}

// ---------------- small utility kernels ----------------
__global__ void copy_in_kernel(const float* __restrict__ in) {
    int i = blockIdx.x * blockDim.x + threadIdx.x;
    if (i < Nn * Dd / 4) ((float4*)g_x)[i] = ((const float4*)in)[i];
}

// ---------------- CSR build ----------------
__global__ void csr_zero_kernel() {
    int i = blockIdx.x * blockDim.x + threadIdx.x;
    if (i < Nn) {
        g_deg[i] = 0;
        g_cursor[i] = 0;
    }
}

__global__ void csr_hist_kernel(const int* __restrict__ ei) {
    int e = blockIdx.x * blockDim.x + threadIdx.x;
    if (e < Ee) atomicAdd(&g_deg[ei[Ee + e]], 1);
}

__global__ void csr_scan1_kernel() {
    __shared__ int sh[SCAN_B];
    int gi = blockIdx.x * SCAN_B + threadIdx.x;
    int v = (gi < Nn) ? g_deg[gi] : 0;
    sh[threadIdx.x] = v;
    __syncthreads();
#pragma unroll
    for (int off = 1; off < SCAN_B; off <<= 1) {
        int t = (threadIdx.x >= off) ? sh[threadIdx.x - off] : 0;
        __syncthreads();
        sh[threadIdx.x] += t;
        __syncthreads();
    }
    if (gi < Nn) g_scan[gi] = sh[threadIdx.x];
    if (threadIdx.x == SCAN_B - 1) g_bsum[blockIdx.x] = sh[threadIdx.x];
}

__global__ void csr_scan2_kernel() {
    if (threadIdx.x == 0) {
        int acc = 0;
        for (int i = 0; i < SCAN_NB; i++) {
            g_boff[i] = acc;
            acc += g_bsum[i];
        }
    }
}

__global__ void csr_scan3_kernel() {
    int gi = blockIdx.x * SCAN_B + threadIdx.x;
    if (gi < Nn) g_rowptr[gi + 1] = g_scan[gi] + g_boff[blockIdx.x];
    if (gi == 0) g_rowptr[0] = 0;
}

__global__ void csr_scatter_kernel(const int* __restrict__ ei) {
    int e = blockIdx.x * blockDim.x + threadIdx.x;
    if (e >= Ee) return;
    int src = ei[e], dst = ei[Ee + e];
    int pos = g_rowptr[dst] + atomicAdd(&g_cursor[dst], 1);
    g_col[pos] = src;
}

// ---------------- GEMM: C[M,NC] = A[M,K] @ B[K,NC], f32x2 packed ----------------
// BM=128, BN=128, BK=16, 256 threads, 8x8 microtile via 32 fma.f32x2.
// A stored in smem with each value DUPLICATED pairwise -> natural (a,a) 64-bit
// operands, broadcast reads (16 lanes share an address), zero packing movs.
template <int K, int NC, bool BIAS, bool RELU, bool RES, int NMAT>
__global__ __launch_bounds__(256, 2) void gemm_kernel(
    const float* __restrict__ A,
    const float* __restrict__ B0, const float* __restrict__ B1, const float* __restrict__ B2,
    const float* __restrict__ bias, const float* __restrict__ res,
    float* __restrict__ C0, float* __restrict__ C1, float* __restrict__ C2) {
    const int BM = 128, BN = 128, BK = 16;
    const int YPM = NC / BN;
    __shared__ __align__(16) float Ast[BK][2 * BM + 8];  // duplicated, transposed
    __shared__ __align__(16) float Bs[BK][BN + 4];

    int mat = (NMAT > 1) ? (blockIdx.y / YPM) : 0;
    int colBase = (blockIdx.y % YPM) * BN;
    const float* B = (NMAT > 1) ? (mat == 0 ? B0 : (mat == 1 ? B1 : B2)) : B0;
    float* C = (NMAT > 1) ? (mat == 0 ? C0 : (mat == 1 ? C1 : C2)) : C0;

    int tid = threadIdx.x;
    int tx = tid & 15;   // col group (8 cols)
    int ty = tid >> 4;   // row group (8 rows)
    int rowBase = blockIdx.x * BM;

    unsigned long long acc[8][4];
#pragma unroll
    for (int i = 0; i < 8; i++)
#pragma unroll
        for (int j = 0; j < 4; j++) acc[i][j] = 0ULL;

    for (int kt = 0; kt < K; kt += BK) {
        // A tile: 128x16, store transposed + duplicated
#pragma unroll
        for (int l = 0; l < 2; l++) {
            int f = tid + 256 * l;
            int ar = f >> 2;
            int ac = (f & 3) * 4;
            int grow = rowBase + ar;
            float4 av = make_float4(0.f, 0.f, 0.f, 0.f);
            if (grow < Nn) av = *(const float4*)&A[grow * K + kt + ac];
            float vv[4] = {av.x, av.y, av.z, av.w};
#pragma unroll
            for (int c = 0; c < 4; c++) {
                Ast[ac + c][ar * 2] = vv[c];
                Ast[ac + c][ar * 2 + 1] = vv[c];
            }
        }
        // B tile: 16x128
#pragma unroll
        for (int l = 0; l < 2; l++) {
            int f = tid + 256 * l;
            int br = f >> 5;
            int bc = (f & 31) * 4;
            float4 bv = *(const float4*)&B[(kt + br) * NC + colBase + bc];
            *(float4*)&Bs[br][bc] = bv;
        }
        __syncthreads();
#pragma unroll
        for (int kk = 0; kk < BK; kk++) {
            ulonglong2 a01 = *(const ulonglong2*)&Ast[kk][ty * 16];
            ulonglong2 a23 = *(const ulonglong2*)&Ast[kk][ty * 16 + 4];
            ulonglong2 a45 = *(const ulonglong2*)&Ast[kk][ty * 16 + 8];
            ulonglong2 a67 = *(const ulonglong2*)&Ast[kk][ty * 16 + 12];
            ulonglong2 b03 = *(const ulonglong2*)&Bs[kk][tx * 8];
            ulonglong2 b47 = *(const ulonglong2*)&Bs[kk][tx * 8 + 4];
            unsigned long long aa[8] = {a01.x, a01.y, a23.x, a23.y,
                                        a45.x, a45.y, a67.x, a67.y};
            unsigned long long bb[4] = {b03.x, b03.y, b47.x, b47.y};
#pragma unroll
            for (int i = 0; i < 8; i++)
#pragma unroll
                for (int j = 0; j < 4; j++) fma2(acc[i][j], aa[i], bb[j]);
        }
        __syncthreads();
    }

    int col = colBase + tx * 8;
    float b8[8] = {0.f, 0.f, 0.f, 0.f, 0.f, 0.f, 0.f, 0.f};
    if (BIAS) {
        float4 ba = *(const float4*)&bias[col];
        float4 bb = *(const float4*)&bias[col + 4];
        b8[0] = ba.x; b8[1] = ba.y; b8[2] = ba.z; b8[3] = ba.w;
        b8[4] = bb.x; b8[5] = bb.y; b8[6] = bb.z; b8[7] = bb.w;
    }
#pragma unroll
    for (int i = 0; i < 8; i++) {
        int row = rowBase + ty * 8 + i;
        if (row >= Nn) continue;
        float r8[8] = {0.f, 0.f, 0.f, 0.f, 0.f, 0.f, 0.f, 0.f};
        if (RES) {
            float4 ra = *(const float4*)&res[row * NC + col];
            float4 rb = *(const float4*)&res[row * NC + col + 4];
            r8[0] = ra.x; r8[1] = ra.y; r8[2] = ra.z; r8[3] = ra.w;
            r8[4] = rb.x; r8[5] = rb.y; r8[6] = rb.z; r8[7] = rb.w;
        }
        float o[8];
#pragma unroll
        for (int j = 0; j < 4; j++) {
            float2 p = *(float2*)&acc[i][j];
            o[2 * j] = p.x;
            o[2 * j + 1] = p.y;
        }
#pragma unroll
        for (int j = 0; j < 8; j++) {
            float vv = o[j];
            if (BIAS) vv += b8[j];
            if (RES) vv += r8[j];
            if (RELU) vv = vv > 0.f ? vv : 0.f;
            o[j] = vv;
        }
        *(float4*)&C[row * NC + col] = make_float4(o[0], o[1], o[2], o[3]);
        *(float4*)&C[row * NC + col + 4] = make_float4(o[4], o[5], o[6], o[7]);
    }
}

// ---------------- fused edge attention: one warp per dst, 4-edge unroll ----------------
__global__ void attn_fused_kernel() {
    int warp = blockIdx.x * (blockDim.x >> 5) + (threadIdx.x >> 5);
    int lane = threadIdx.x & 31;
    if (warp >= Nn) return;
    int dst = warp;

    float4 q4 = *(const float4*)&g_q[dst * Dd + lane * 4];

    float m = -INFINITY;
    float l = 0.0f;
    float4 acc = make_float4(0.f, 0.f, 0.f, 0.f);

    int beg = g_rowptr[dst];
    int end = g_rowptr[dst + 1];
    int j = beg;
    for (; j + 4 <= end; j += 4) {
        int s0 = g_col[j], s1 = g_col[j + 1], s2 = g_col[j + 2], s3 = g_col[j + 3];
        // issue all 8 gathers up front for MLP
        float4 k0 = *(const float4*)&g_k[s0 * Dd + lane * 4];
        float4 k1 = *(const float4*)&g_k[s1 * Dd + lane * 4];
        float4 k2 = *(const float4*)&g_k[s2 * Dd + lane * 4];
        float4 k3 = *(const float4*)&g_k[s3 * Dd + lane * 4];
        float4 v0 = *(const float4*)&g_v[s0 * Dd + lane * 4];
        float4 v1 = *(const float4*)&g_v[s1 * Dd + lane * 4];
        float4 v2 = *(const float4*)&g_v[s2 * Dd + lane * 4];
        float4 v3 = *(const float4*)&g_v[s3 * Dd + lane * 4];

        float p0 = q4.x * k0.x + q4.y * k0.y + q4.z * k0.z + q4.w * k0.w;
        float p1 = q4.x * k1.x + q4.y * k1.y + q4.z * k1.z + q4.w * k1.w;
        float p2 = q4.x * k2.x + q4.y * k2.y + q4.z * k2.z + q4.w * k2.w;
        float p3 = q4.x * k3.x + q4.y * k3.y + q4.z * k3.z + q4.w * k3.w;
        p0 += __shfl_xor_sync(0xffffffffu, p0, 1);
        p1 += __shfl_xor_sync(0xffffffffu, p1, 1);
        p2 += __shfl_xor_sync(0xffffffffu, p2, 1);
        p3 += __shfl_xor_sync(0xffffffffu, p3, 1);
        p0 += __shfl_xor_sync(0xffffffffu, p0, 2);
        p1 += __shfl_xor_sync(0xffffffffu, p1, 2);
        p2 += __shfl_xor_sync(0xffffffffu, p2, 2);
        p3 += __shfl_xor_sync(0xffffffffu, p3, 2);
        p0 *= 0.25f; p1 *= 0.25f; p2 *= 0.25f; p3 *= 0.25f;

        float mx = fmaxf(fmaxf(p0, p1), fmaxf(p2, p3));
        float newm = fmaxf(m, mx);
        float corr = __expf(m - newm);
        float e0 = __expf(p0 - newm);
        float e1 = __expf(p1 - newm);
        float e2 = __expf(p2 - newm);
        float e3 = __expf(p3 - newm);
        acc.x = acc.x * corr + e0 * v0.x + e1 * v1.x + e2 * v2.x + e3 * v3.x;
        acc.y = acc.y * corr + e0 * v0.y + e1 * v1.y + e2 * v2.y + e3 * v3.y;
        acc.z = acc.z * corr + e0 * v0.z + e1 * v1.z + e2 * v2.z + e3 * v3.z;
        acc.w = acc.w * corr + e0 * v0.w + e1 * v1.w + e2 * v2.w + e3 * v3.w;
        l = l * corr + e0 + e1 + e2 + e3;
        m = newm;
    }
    for (; j < end; j++) {
        int src = g_col[j];
        float4 k4 = *(const float4*)&g_k[src * Dd + lane * 4];
        float4 v4 = *(const float4*)&g_v[src * Dd + lane * 4];
        float p = q4.x * k4.x + q4.y * k4.y + q4.z * k4.z + q4.w * k4.w;
        p += __shfl_xor_sync(0xffffffffu, p, 1);
        p += __shfl_xor_sync(0xffffffffu, p, 2);
        float s = p * 0.25f;
        float newm = fmaxf(m, s);
        float corr = __expf(m - newm);
        float pe = __expf(s - newm);
        acc.x = acc.x * corr + pe * v4.x;
        acc.y = acc.y * corr + pe * v4.y;
        acc.z = acc.z * corr + pe * v4.z;
        acc.w = acc.w * corr + pe * v4.w;
        l = l * corr + pe;
        m = newm;
    }
    float inv = (l > 0.f) ? (1.0f / l) : 0.0f;
    acc.x *= inv; acc.y *= inv; acc.z *= inv; acc.w *= inv;
    *(float4*)&g_attn[dst * Dd + lane * 4] = acc;
}

// ---------------- BatchNorm ----------------
__global__ void bn_zero_kernel() {
    int t = threadIdx.x;
    if (t < Dd) {
        g_colsum[t] = 0.0;
        g_colsq[t] = 0.0;
    }
}

__global__ void bn_stats_kernel(const float* __restrict__ in) {
    int c = threadIdx.x;
    int r0 = blockIdx.x * 128;
    int r1 = min(r0 + 128, Nn);
    float s0 = 0.f, s1 = 0.f, q0 = 0.f, q1 = 0.f;
    int r = r0;
    for (; r + 1 < r1; r += 2) {
        float a = in[r * Dd + c];
        float b = in[(r + 1) * Dd + c];
        s0 += a; q0 += a * a;
        s1 += b; q1 += b * b;
    }
    if (r < r1) {
        float a = in[r * Dd + c];
        s0 += a; q0 += a * a;
    }
    atomicAdd(&g_colsum[c], (double)(s0 + s1));
    atomicAdd(&g_colsq[c], (double)(q0 + q1));
}

__global__ void bn_apply_kernel(const float* __restrict__ in, const float* __restrict__ g,
                                const float* __restrict__ b, float* __restrict__ out) {
    int i = blockIdx.x * blockDim.x + threadIdx.x;
    if (i >= Nn * Dd / 4) return;
    int c0 = (i * 4) & (Dd - 1);
    float4 iv = ((const float4*)in)[i];
    float o[4];
    float vin[4] = {iv.x, iv.y, iv.z, iv.w};
#pragma unroll
    for (int t = 0; t < 4; t++) {
        int c = c0 + t;
        double md = g_colsum[c] / (double)Nn;
        double vard = g_colsq[c] / (double)Nn - md * md;
        float scale = rsqrtf((float)vard + EPSf) * g[c];
        o[t] = (vin[t] - (float)md) * scale + b[c];
    }
    ((float4*)out)[i] = make_float4(o[0], o[1], o[2], o[3]);
}

// ---------------- final projection ----------------
__global__ void proj_kernel(const float* __restrict__ Wp, const float* __restrict__ bp,
                            float* __restrict__ out) {
    int warp = blockIdx.x * (blockDim.x >> 5) + (threadIdx.x >> 5);
    int lane = threadIdx.x & 31;
    if (warp >= Nn) return;
    float acc[Cc] = {0.f, 0.f, 0.f, 0.f, 0.f};
    for (int k = lane; k < Dd; k += 32) {
        float xv = g_x[warp * Dd + k];
#pragma unroll
        for (int c = 0; c < Cc; c++) acc[c] += xv * Wp[k * Cc + c];
    }
#pragma unroll
    for (int c = 0; c < Cc; c++) {
#pragma unroll
        for (int o = 16; o > 0; o >>= 1) acc[c] += __shfl_down_sync(0xffffffffu, acc[c], o);
    }
    if (lane == 0) {
#pragma unroll
        for (int c = 0; c < Cc; c++) out[warp * Cc + c] = acc[c] + bp[c];
    }
}

// ---------------- launch ----------------
extern "C" void kernel_launch(void* const* d_in, const int* in_sizes, int n_in,
                              void* d_out, int out_size) {
    const float* x   = (const float*)d_in[0];
    const int*   ei  = (const int*)d_in[1];
    const float* Wq  = (const float*)d_in[2];
    const float* Wk  = (const float*)d_in[3];
    const float* Wv  = (const float*)d_in[4];
    const float* Wo  = (const float*)d_in[5];
    const float* g1  = (const float*)d_in[6];
    const float* bn1 = (const float*)d_in[7];
    const float* W1  = (const float*)d_in[8];
    const float* bf1 = (const float*)d_in[9];
    const float* W2  = (const float*)d_in[10];
    const float* bf2 = (const float*)d_in[11];
    const float* g2  = (const float*)d_in[12];
    const float* bn2 = (const float*)d_in[13];
    const float* Wp  = (const float*)d_in[14];
    const float* bp  = (const float*)d_in[15];
    float* out = (float*)d_out;

    float *px, *pq, *pk, *pv, *pattn, *ptmp, *pff;
    cudaGetSymbolAddress((void**)&px, g_x);
    cudaGetSymbolAddress((void**)&pq, g_q);
    cudaGetSymbolAddress((void**)&pk, g_k);
    cudaGetSymbolAddress((void**)&pv, g_v);
    cudaGetSymbolAddress((void**)&pattn, g_attn);
    cudaGetSymbolAddress((void**)&ptmp, g_tmp);
    cudaGetSymbolAddress((void**)&pff, g_ff);

    const int gemmRows = (Nn + 127) / 128;  // 391
    const int elemBlocks = (Nn * Dd + 255) / 256;
    const int vecBlocks = (Nn * Dd / 4 + 255) / 256;
    const int edgeBlocks = (Ee + 255) / 256;
    const int nodeBlocks = (Nn + 255) / 256;
    const int statBlocks = (Nn + 127) / 128;
    const int warpBlocks = (Nn + 7) / 8;

    copy_in_kernel<<<vecBlocks, 256>>>(x);

    // ---- build CSR once; reused across layers ----
    csr_zero_kernel<<<nodeBlocks, 256>>>();
    csr_hist_kernel<<<edgeBlocks, 256>>>(ei);
    csr_scan1_kernel<<<SCAN_NB, SCAN_B>>>();
    csr_scan2_kernel<<<1, 32>>>();
    csr_scan3_kernel<<<SCAN_NB, SCAN_B>>>();
    csr_scatter_kernel<<<edgeBlocks, 256>>>(ei);

    for (int i = 0; i < Ll; i++) {
        const float* wq = Wq + (size_t)i * Dd * Dd;
        const float* wk = Wk + (size_t)i * Dd * Dd;
        const float* wv = Wv + (size_t)i * Dd * Dd;
        const float* wo = Wo + (size_t)i * Dd * Dd;

        gemm_kernel<Dd, Dd, false, false, false, 3><<<dim3(gemmRows, 3), 256>>>(
            px, wq, wk, wv, nullptr, nullptr, pq, pk, pv);

        attn_fused_kernel<<<warpBlocks, 256>>>();

        gemm_kernel<Dd, Dd, false, false, true, 1><<<dim3(gemmRows, 1), 256>>>(
            pattn, wo, nullptr, nullptr, nullptr, px, ptmp, nullptr, nullptr);

        bn_zero_kernel<<<1, 128>>>();
        bn_stats_kernel<<<statBlocks, 128>>>(ptmp);
        bn_apply_kernel<<<vecBlocks, 256>>>(ptmp, g1 + i * Dd, bn1 + i * Dd, px);

        gemm_kernel<Dd, FFd, true, true, false, 1><<<dim3(gemmRows, 2), 256>>>(
            px, W1 + (size_t)i * Dd * FFd, nullptr, nullptr,
            bf1 + i * FFd, nullptr, pff, nullptr, nullptr);
        gemm_kernel<FFd, Dd, true, false, true, 1><<<dim3(gemmRows, 1), 256>>>(
            pff, W2 + (size_t)i * FFd * Dd, nullptr, nullptr,
            bf2 + i * Dd, px, ptmp, nullptr, nullptr);

        bn_zero_kernel<<<1, 128>>>();
        bn_stats_kernel<<<statBlocks, 128>>>(ptmp);
        bn_apply_kernel<<<vecBlocks, 256>>>(ptmp, g2 + i * Dd, bn2 + i * Dd, px);
    }

    proj_kernel<<<warpBlocks, 256>>>(Wp, bp, out);
}

// round 4
// speedup vs baseline: 1.1376x; 1.1376x over previous
#include <cuda_runtime.h>
#include <math.h>

#define Nn 50000
#define Ee 640000
#define Dd 128
#define Hh 8
#define DHd 16
#define FFd 256
#define Cc 5
#define Ll 6
#define EPSf 1e-5f

#define SCAN_B 1024
#define SCAN_NB ((Nn + SCAN_B - 1) / SCAN_B)  // 49

// ---------------- scratch (device globals; no allocs allowed) ----------------
__device__ float g_x[Nn * Dd];
__device__ float g_q[Nn * Dd];
__device__ float g_k[Nn * Dd];
__device__ float g_v[Nn * Dd];
__device__ float g_attn[Nn * Dd];
__device__ float g_tmp[Nn * Dd];
__device__ float g_ff[Nn * FFd];
__device__ double g_colsum[Dd];
__device__ double g_colsq[Dd];
// CSR
__device__ int g_deg[Nn];
__device__ int g_cursor[Nn];
__device__ int g_rowptr[Nn + 1];
__device__ int g_scan[Nn];
__device__ int g_bsum[SCAN_NB];
__device__ int g_boff[SCAN_NB];
__device__ int g_col[Ee];

// packed fp32x2 FMA (Blackwell FFMA2, PTX-only)
__device__ __forceinline__ void fma2(unsigned long long& d, unsigned long long a,
                                     unsigned long long b) {
    asm("fma.rn.f32x2 %0, %1, %2, %0;" : "+l"(d) : "l"(a), "l"(b));
}
__device__ __forceinline__ unsigned long long pack2(float v) {
    unsigned long long r;
    asm("mov.b64 %0, {%1, %1};" : "=l"(r) : "f"(v));
    return r;
}

// ---------------- fused copy-in + CSR zero ----------------
__global__ void copy_zero_kernel(const float* __restrict__ in) {
    int i = blockIdx.x * blockDim.x + threadIdx.x;
    if (i < Nn * Dd / 4) ((float4*)g_x)[i] = ((const float4*)in)[i];
    if (i < Nn) {
        g_deg[i] = 0;
        g_cursor[i] = 0;
    }
}

// ---------------- CSR build ----------------
__global__ void csr_hist_kernel(const int* __restrict__ ei) {
    int e = blockIdx.x * blockDim.x + threadIdx.x;
    if (e < Ee) atomicAdd(&g_deg[ei[Ee + e]], 1);
}

__global__ void csr_scan1_kernel() {
    __shared__ int sh[SCAN_B];
    int gi = blockIdx.x * SCAN_B + threadIdx.x;
    int v = (gi < Nn) ? g_deg[gi] : 0;
    sh[threadIdx.x] = v;
    __syncthreads();
#pragma unroll
    for (int off = 1; off < SCAN_B; off <<= 1) {
        int t = (threadIdx.x >= off) ? sh[threadIdx.x - off] : 0;
        __syncthreads();
        sh[threadIdx.x] += t;
        __syncthreads();
    }
    if (gi < Nn) g_scan[gi] = sh[threadIdx.x];
    if (threadIdx.x == SCAN_B - 1) g_bsum[blockIdx.x] = sh[threadIdx.x];
}

__global__ void csr_scan2_kernel() {
    if (threadIdx.x == 0) {
        int acc = 0;
        for (int i = 0; i < SCAN_NB; i++) {
            g_boff[i] = acc;
            acc += g_bsum[i];
        }
    }
}

__global__ void csr_scan3_kernel() {
    int gi = blockIdx.x * SCAN_B + threadIdx.x;
    if (gi < Nn) g_rowptr[gi + 1] = g_scan[gi] + g_boff[blockIdx.x];
    if (gi == 0) g_rowptr[0] = 0;
}

__global__ void csr_scatter_kernel(const int* __restrict__ ei) {
    int e = blockIdx.x * blockDim.x + threadIdx.x;
    if (e >= Ee) return;
    int src = ei[e], dst = ei[Ee + e];
    int pos = g_rowptr[dst] + atomicAdd(&g_cursor[dst], 1);
    g_col[pos] = src;
}

// ---------------- GEMM: C[M,NC] = A[M,K] @ B[K,NC], f32x2 packed ----------------
// BM=128, BN=128, BK=16, 256 threads, 8x8 microtile via 32 fma.f32x2.
// A: transposed smem, scalar reads (broadcast), packed to (a,a) via mov.b64.
// B: permuted conflict-free layout — even 16B chunks in first half-row,
//    odd chunks in second half; lane tx reads [tx*4] and [64+tx*4].
template <int K, int NC, bool BIAS, bool RELU, bool RES, int NMAT>
__global__ __launch_bounds__(256, 2) void gemm_kernel(
    const float* __restrict__ A,
    const float* __restrict__ B0, const float* __restrict__ B1, const float* __restrict__ B2,
    const float* __restrict__ bias, const float* __restrict__ res,
    float* __restrict__ C0, float* __restrict__ C1, float* __restrict__ C2) {
    const int BM = 128, BN = 128, BK = 16;
    const int YPM = NC / BN;
    __shared__ __align__(16) float Ast[BK][BM + 4];
    __shared__ __align__(16) float Bs[BK][BN + 4];  // physically permuted

    int mat = (NMAT > 1) ? (blockIdx.y / YPM) : 0;
    int colBase = (blockIdx.y % YPM) * BN;
    const float* B = (NMAT > 1) ? (mat == 0 ? B0 : (mat == 1 ? B1 : B2)) : B0;
    float* C = (NMAT > 1) ? (mat == 0 ? C0 : (mat == 1 ? C1 : C2)) : C0;

    int tid = threadIdx.x;
    int tx = tid & 15;   // col group (8 cols)
    int ty = tid >> 4;   // row group (8 rows)
    int rowBase = blockIdx.x * BM;

    unsigned long long acc[8][4];
#pragma unroll
    for (int i = 0; i < 8; i++)
#pragma unroll
        for (int j = 0; j < 4; j++) acc[i][j] = 0ULL;

    for (int kt = 0; kt < K; kt += BK) {
        // A tile: 128x16 = 512 float4, 2 per thread (store transposed)
#pragma unroll
        for (int l = 0; l < 2; l++) {
            int f = tid + 256 * l;
            int ar = f >> 2;
            int ac = (f & 3) * 4;
            int grow = rowBase + ar;
            float4 av = make_float4(0.f, 0.f, 0.f, 0.f);
            if (grow < Nn) av = *(const float4*)&A[grow * K + kt + ac];
            Ast[ac + 0][ar] = av.x;
            Ast[ac + 1][ar] = av.y;
            Ast[ac + 2][ar] = av.z;
            Ast[ac + 3][ar] = av.w;
        }
        // B tile: 16x128, permuted store (even chunks first, odd chunks second)
#pragma unroll
        for (int l = 0; l < 2; l++) {
            int f = tid + 256 * l;
            int br = f >> 5;         // 0..15
            int p = f & 31;          // physical chunk index
            int c = (p < 16) ? (2 * p) : (2 * (p - 16) + 1);  // logical chunk
            float4 bv = *(const float4*)&B[(kt + br) * NC + colBase + c * 4];
            *(float4*)&Bs[br][p * 4] = bv;
        }
        __syncthreads();
#pragma unroll
        for (int kk = 0; kk < BK; kk++) {
            float4 a0 = *(const float4*)&Ast[kk][ty * 8];
            float4 a1 = *(const float4*)&Ast[kk][ty * 8 + 4];
            ulonglong2 bA = *(const ulonglong2*)&Bs[kk][tx * 4];        // cols 8tx..8tx+3
            ulonglong2 bB = *(const ulonglong2*)&Bs[kk][64 + tx * 4];   // cols 8tx+4..8tx+7
            float a8[8] = {a0.x, a0.y, a0.z, a0.w, a1.x, a1.y, a1.z, a1.w};
            unsigned long long bb[4] = {bA.x, bA.y, bB.x, bB.y};
            unsigned long long ap[8];
#pragma unroll
            for (int i = 0; i < 8; i++) ap[i] = pack2(a8[i]);
#pragma unroll
            for (int i = 0; i < 8; i++)
#pragma unroll
                for (int j = 0; j < 4; j++) fma2(acc[i][j], ap[i], bb[j]);
        }
        __syncthreads();
    }

    int col = colBase + tx * 8;
    float b8[8] = {0.f, 0.f, 0.f, 0.f, 0.f, 0.f, 0.f, 0.f};
    if (BIAS) {
        float4 ba = *(const float4*)&bias[col];
        float4 bb = *(const float4*)&bias[col + 4];
        b8[0] = ba.x; b8[1] = ba.y; b8[2] = ba.z; b8[3] = ba.w;
        b8[4] = bb.x; b8[5] = bb.y; b8[6] = bb.z; b8[7] = bb.w;
    }
#pragma unroll
    for (int i = 0; i < 8; i++) {
        int row = rowBase + ty * 8 + i;
        if (row >= Nn) continue;
        float r8[8] = {0.f, 0.f, 0.f, 0.f, 0.f, 0.f, 0.f, 0.f};
        if (RES) {
            float4 ra = *(const float4*)&res[row * NC + col];
            float4 rb = *(const float4*)&res[row * NC + col + 4];
            r8[0] = ra.x; r8[1] = ra.y; r8[2] = ra.z; r8[3] = ra.w;
            r8[4] = rb.x; r8[5] = rb.y; r8[6] = rb.z; r8[7] = rb.w;
        }
        float o[8];
#pragma unroll
        for (int j = 0; j < 4; j++) {
            float2 p = *(float2*)&acc[i][j];
            o[2 * j] = p.x;
            o[2 * j + 1] = p.y;
        }
#pragma unroll
        for (int j = 0; j < 8; j++) {
            float vv = o[j];
            if (BIAS) vv += b8[j];
            if (RES) vv += r8[j];
            if (RELU) vv = vv > 0.f ? vv : 0.f;
            o[j] = vv;
        }
        *(float4*)&C[row * NC + col] = make_float4(o[0], o[1], o[2], o[3]);
        *(float4*)&C[row * NC + col + 4] = make_float4(o[4], o[5], o[6], o[7]);
    }
}

// ---------------- fused edge attention: one warp per dst node (R2 version) ----------------
__global__ void attn_fused_kernel() {
    int warp = blockIdx.x * (blockDim.x >> 5) + (threadIdx.x >> 5);
    int lane = threadIdx.x & 31;
    if (warp >= Nn) return;
    int dst = warp;

    float4 q4 = *(const float4*)&g_q[dst * Dd + lane * 4];

    float m = -INFINITY;
    float l = 0.0f;
    float4 acc = make_float4(0.f, 0.f, 0.f, 0.f);

    int beg = g_rowptr[dst];
    int end = g_rowptr[dst + 1];
    for (int j = beg; j < end; j++) {
        int src = g_col[j];
        float4 k4 = *(const float4*)&g_k[src * Dd + lane * 4];
        float p = q4.x * k4.x + q4.y * k4.y + q4.z * k4.z + q4.w * k4.w;
        p += __shfl_xor_sync(0xffffffffu, p, 1);
        p += __shfl_xor_sync(0xffffffffu, p, 2);
        float s = p * 0.25f;

        float newm = fmaxf(m, s);
        float corr = __expf(m - newm);
        float pe = __expf(s - newm);
        float4 v4 = *(const float4*)&g_v[src * Dd + lane * 4];
        acc.x = acc.x * corr + pe * v4.x;
        acc.y = acc.y * corr + pe * v4.y;
        acc.z = acc.z * corr + pe * v4.z;
        acc.w = acc.w * corr + pe * v4.w;
        l = l * corr + pe;
        m = newm;
    }
    float inv = (l > 0.f) ? (1.0f / l) : 0.0f;
    acc.x *= inv; acc.y *= inv; acc.z *= inv; acc.w *= inv;
    *(float4*)&g_attn[dst * Dd + lane * 4] = acc;
}

// ---------------- BatchNorm ----------------
__global__ void bn_zero_kernel() {
    int t = threadIdx.x;
    if (t < Dd) {
        g_colsum[t] = 0.0;
        g_colsq[t] = 0.0;
    }
}

__global__ void bn_stats_kernel(const float* __restrict__ in) {
    int c = threadIdx.x;
    int r0 = blockIdx.x * 128;
    int r1 = min(r0 + 128, Nn);
    float s0 = 0.f, s1 = 0.f, q0 = 0.f, q1 = 0.f;
    int r = r0;
    for (; r + 1 < r1; r += 2) {
        float a = in[r * Dd + c];
        float b = in[(r + 1) * Dd + c];
        s0 += a; q0 += a * a;
        s1 += b; q1 += b * b;
    }
    if (r < r1) {
        float a = in[r * Dd + c];
        s0 += a; q0 += a * a;
    }
    atomicAdd(&g_colsum[c], (double)(s0 + s1));
    atomicAdd(&g_colsq[c], (double)(q0 + q1));
}

__global__ void bn_apply_kernel(const float* __restrict__ in, const float* __restrict__ g,
                                const float* __restrict__ b, float* __restrict__ out) {
    int i = blockIdx.x * blockDim.x + threadIdx.x;
    if (i >= Nn * Dd / 4) return;
    int c0 = (i * 4) & (Dd - 1);
    float4 iv = ((const float4*)in)[i];
    float o[4];
    float vin[4] = {iv.x, iv.y, iv.z, iv.w};
#pragma unroll
    for (int t = 0; t < 4; t++) {
        int c = c0 + t;
        double md = g_colsum[c] / (double)Nn;
        double vard = g_colsq[c] / (double)Nn - md * md;
        float scale = rsqrtf((float)vard + EPSf) * g[c];
        o[t] = (vin[t] - (float)md) * scale + b[c];
    }
    ((float4*)out)[i] = make_float4(o[0], o[1], o[2], o[3]);
}

// ---------------- final projection ----------------
__global__ void proj_kernel(const float* __restrict__ Wp, const float* __restrict__ bp,
                            float* __restrict__ out) {
    int warp = blockIdx.x * (blockDim.x >> 5) + (threadIdx.x >> 5);
    int lane = threadIdx.x & 31;
    if (warp >= Nn) return;
    float acc[Cc] = {0.f, 0.f, 0.f, 0.f, 0.f};
    for (int k = lane; k < Dd; k += 32) {
        float xv = g_x[warp * Dd + k];
#pragma unroll
        for (int c = 0; c < Cc; c++) acc[c] += xv * Wp[k * Cc + c];
    }
#pragma unroll
    for (int c = 0; c < Cc; c++) {
#pragma unroll
        for (int o = 16; o > 0; o >>= 1) acc[c] += __shfl_down_sync(0xffffffffu, acc[c], o);
    }
    if (lane == 0) {
#pragma unroll
        for (int c = 0; c < Cc; c++) out[warp * Cc + c] = acc[c] + bp[c];
    }
}

// ---------------- launch ----------------
extern "C" void kernel_launch(void* const* d_in, const int* in_sizes, int n_in,
                              void* d_out, int out_size) {
    const float* x   = (const float*)d_in[0];
    const int*   ei  = (const int*)d_in[1];
    const float* Wq  = (const float*)d_in[2];
    const float* Wk  = (const float*)d_in[3];
    const float* Wv  = (const float*)d_in[4];
    const float* Wo  = (const float*)d_in[5];
    const float* g1  = (const float*)d_in[6];
    const float* bn1 = (const float*)d_in[7];
    const float* W1  = (const float*)d_in[8];
    const float* bf1 = (const float*)d_in[9];
    const float* W2  = (const float*)d_in[10];
    const float* bf2 = (const float*)d_in[11];
    const float* g2  = (const float*)d_in[12];
    const float* bn2 = (const float*)d_in[13];
    const float* Wp  = (const float*)d_in[14];
    const float* bp  = (const float*)d_in[15];
    float* out = (float*)d_out;

    float *px, *pq, *pk, *pv, *pattn, *ptmp, *pff;
    cudaGetSymbolAddress((void**)&px, g_x);
    cudaGetSymbolAddress((void**)&pq, g_q);
    cudaGetSymbolAddress((void**)&pk, g_k);
    cudaGetSymbolAddress((void**)&pv, g_v);
    cudaGetSymbolAddress((void**)&pattn, g_attn);
    cudaGetSymbolAddress((void**)&ptmp, g_tmp);
    cudaGetSymbolAddress((void**)&pff, g_ff);

    const int gemmRows = (Nn + 127) / 128;  // 391
    const int vecBlocks = (Nn * Dd / 4 + 255) / 256;
    const int edgeBlocks = (Ee + 255) / 256;
    const int statBlocks = (Nn + 127) / 128;
    const int warpBlocks = (Nn + 7) / 8;

    // launch #1: copy x in + zero CSR counters
    copy_zero_kernel<<<vecBlocks, 256>>>(x);
    // #2, #3
    csr_hist_kernel<<<edgeBlocks, 256>>>(ei);
    csr_scan1_kernel<<<SCAN_NB, SCAN_B>>>();
    // #4: layer-0 QKV GEMM (hoisted so the ncu window captures it)
    gemm_kernel<Dd, Dd, false, false, false, 3><<<dim3(gemmRows, 3), 256>>>(
        px, Wq, Wk, Wv, nullptr, nullptr, pq, pk, pv);
    // #5..#7: finish CSR
    csr_scan2_kernel<<<1, 32>>>();
    csr_scan3_kernel<<<SCAN_NB, SCAN_B>>>();
    csr_scatter_kernel<<<edgeBlocks, 256>>>(ei);

    for (int i = 0; i < Ll; i++) {
        const float* wq = Wq + (size_t)i * Dd * Dd;
        const float* wk = Wk + (size_t)i * Dd * Dd;
        const float* wv = Wv + (size_t)i * Dd * Dd;
        const float* wo = Wo + (size_t)i * Dd * Dd;

        if (i > 0) {
            gemm_kernel<Dd, Dd, false, false, false, 3><<<dim3(gemmRows, 3), 256>>>(
                px, wq, wk, wv, nullptr, nullptr, pq, pk, pv);
        }

        attn_fused_kernel<<<warpBlocks, 256>>>();

        gemm_kernel<Dd, Dd, false, false, true, 1><<<dim3(gemmRows, 1), 256>>>(
            pattn, wo, nullptr, nullptr, nullptr, px, ptmp, nullptr, nullptr);

        bn_zero_kernel<<<1, 128>>>();
        bn_stats_kernel<<<statBlocks, 128>>>(ptmp);
        bn_apply_kernel<<<vecBlocks, 256>>>(ptmp, g1 + i * Dd, bn1 + i * Dd, px);

        gemm_kernel<Dd, FFd, true, true, false, 1><<<dim3(gemmRows, 2), 256>>>(
            px, W1 + (size_t)i * Dd * FFd, nullptr, nullptr,
            bf1 + i * FFd, nullptr, pff, nullptr, nullptr);
        gemm_kernel<FFd, Dd, true, false, true, 1><<<dim3(gemmRows, 1), 256>>>(
            pff, W2 + (size_t)i * FFd * Dd, nullptr, nullptr,
            bf2 + i * Dd, px, ptmp, nullptr, nullptr);

        bn_zero_kernel<<<1, 128>>>();
        bn_stats_kernel<<<statBlocks, 128>>>(ptmp);
        bn_apply_kernel<<<vecBlocks, 256>>>(ptmp, g2 + i * Dd, bn2 + i * Dd, px);
    }

    proj_kernel<<<warpBlocks, 256>>>(Wp, bp, out);
}

// round 5
// speedup vs baseline: 2.1475x; 1.8878x over previous
#include <cuda_runtime.h>
#include <math.h>

#define Nn 50000
#define Ee 640000
#define Dd 128
#define Hh 8
#define DHd 16
#define FFd 256
#define Cc 5
#define Ll 6
#define EPSf 1e-5f

#define SCAN_B 1024
#define SCAN_NB ((Nn + SCAN_B - 1) / SCAN_B)  // 49

// ---------------- scratch (device globals; no allocs allowed) ----------------
__device__ float g_q[Nn * Dd];
__device__ float g_k[Nn * Dd];
__device__ float g_v[Nn * Dd];
__device__ float g_attn[Nn * Dd];
__device__ float g_tmp1[Nn * Dd];
__device__ float g_tmp2[Nn * Dd];
__device__ float g_ff[Nn * FFd];
__device__ double g_sum1[Dd];
__device__ double g_sq1[Dd];
__device__ double g_sum2[Dd];
__device__ double g_sq2[Dd];
// CSR
__device__ int g_deg[Nn];
__device__ int g_cursor[Nn];
__device__ int g_rowptr[Nn + 1];
__device__ int g_scan[Nn];
__device__ int g_bsum[SCAN_NB];
__device__ int g_col[Ee];

// packed fp32x2 FMA (Blackwell FFMA2, PTX-only)
__device__ __forceinline__ void fma2(unsigned long long& d, unsigned long long a,
                                     unsigned long long b) {
    asm("fma.rn.f32x2 %0, %1, %2, %0;" : "+l"(d) : "l"(a), "l"(b));
}
__device__ __forceinline__ unsigned long long pack2(float v) {
    unsigned long long r;
    asm("mov.b64 %0, {%1, %1};" : "=l"(r) : "f"(v));
    return r;
}

// ---------------- CSR build ----------------
__global__ void csr_zero_kernel() {
    int i = blockIdx.x * blockDim.x + threadIdx.x;
    if (i < Nn) {
        g_deg[i] = 0;
        g_cursor[i] = 0;
    }
}

__global__ void csr_hist_kernel(const int* __restrict__ ei) {
    int e = blockIdx.x * blockDim.x + threadIdx.x;
    if (e < Ee) atomicAdd(&g_deg[ei[Ee + e]], 1);
}

__global__ void csr_scan1_kernel() {
    __shared__ int sh[SCAN_B];
    int gi = blockIdx.x * SCAN_B + threadIdx.x;
    int v = (gi < Nn) ? g_deg[gi] : 0;
    sh[threadIdx.x] = v;
    __syncthreads();
#pragma unroll
    for (int off = 1; off < SCAN_B; off <<= 1) {
        int t = (threadIdx.x >= off) ? sh[threadIdx.x - off] : 0;
        __syncthreads();
        sh[threadIdx.x] += t;
        __syncthreads();
    }
    if (gi < Nn) g_scan[gi] = sh[threadIdx.x];
    if (threadIdx.x == SCAN_B - 1) g_bsum[blockIdx.x] = sh[threadIdx.x];
}

// scan2+scan3 merged: each block computes its own block-offset from g_bsum
__global__ void csr_scan23_kernel() {
    __shared__ int soff;
    if (threadIdx.x == 0) {
        int acc = 0;
        for (int i = 0; i < (int)blockIdx.x; i++) acc += g_bsum[i];
        soff = acc;
    }
    __syncthreads();
    int gi = blockIdx.x * SCAN_B + threadIdx.x;
    if (gi < Nn) g_rowptr[gi + 1] = g_scan[gi] + soff;
    if (gi == 0) g_rowptr[0] = 0;
}

__global__ void csr_scatter_kernel(const int* __restrict__ ei) {
    int e = blockIdx.x * blockDim.x + threadIdx.x;
    if (e >= Ee) return;
    int src = ei[e], dst = ei[Ee + e];
    int pos = g_rowptr[dst] + atomicAdd(&g_cursor[dst], 1);
    g_col[pos] = src;
}

// ---------------- stats zero ----------------
__global__ void zero_stats_kernel(double* __restrict__ a, double* __restrict__ b) {
    int t = threadIdx.x;
    if (t < Dd) {
        a[t] = 0.0;
        b[t] = 0.0;
    }
}

// ---------------- fused GEMM ----------------
// C[M,NC] = op(A)[M,K] @ B[K,NC] (+bias)(+op(res))(relu), f32x2 packed,
// double-buffered smem pipeline.
// BNA:   A columns get x̂ = a*scale[k]+shift[k]   (BN applied to input)
// BNRES: residual columns get x̂ = r*scale[c]+shift[c]
// STATS: epilogue accumulates column sum/sumsq of written C into stsum/stsq
template <int K, int NC, bool BIAS, bool RELU, bool RES, bool BNA, bool BNRES,
          bool STATS, int NMAT>
__global__ __launch_bounds__(256, 2) void gemm_kernel(
    const float* __restrict__ A,
    const float* __restrict__ B0, const float* __restrict__ B1, const float* __restrict__ B2,
    const float* __restrict__ bias, const float* __restrict__ res,
    const float* __restrict__ bng, const float* __restrict__ bnb,
    const double* __restrict__ bnsum, const double* __restrict__ bnsq,
    double* __restrict__ stsum, double* __restrict__ stsq,
    float* __restrict__ C0, float* __restrict__ C1, float* __restrict__ C2) {
    const int BM = 128, BN = 128, BK = 16;
    const int YPM = NC / BN;
    constexpr int PSZ = BNA ? K : (BNRES ? NC : 1);
    constexpr int SSZ = STATS ? BN : 1;

    __shared__ __align__(16) float Ast[2][BK][BM + 4];
    __shared__ __align__(16) float Bs[2][BK][BN + 4];  // permuted layout
    __shared__ float s_sc[PSZ], s_sh[PSZ];
    __shared__ float s_cs[SSZ], s_cq[SSZ];

    int tid = threadIdx.x;
    int tx = tid & 15;
    int ty = tid >> 4;
    int rowBase = blockIdx.x * BM;
    int mat = (NMAT > 1) ? (blockIdx.y / YPM) : 0;
    int colBase = (blockIdx.y % YPM) * BN;
    const float* B = (NMAT > 1) ? (mat == 0 ? B0 : (mat == 1 ? B1 : B2)) : B0;
    float* C = (NMAT > 1) ? (mat == 0 ? C0 : (mat == 1 ? C1 : C2)) : C0;

    // precompute BN scale/shift into smem
    if (BNA || BNRES) {
        for (int c = tid; c < PSZ; c += 256) {
            double m = bnsum[c] / (double)Nn;
            double var = bnsq[c] / (double)Nn - m * m;
            float sc = rsqrtf((float)var + EPSf) * bng[c];
            s_sc[c] = sc;
            s_sh[c] = bnb[c] - (float)m * sc;
        }
        __syncthreads();
    }

    unsigned long long acc[8][4];
#pragma unroll
    for (int i = 0; i < 8; i++)
#pragma unroll
        for (int j = 0; j < 4; j++) acc[i][j] = 0ULL;

    // tile load helper (global -> regs -> smem[buf]), BNA applied at store
    auto load_store = [&](int kt, int buf) {
#pragma unroll
        for (int l = 0; l < 2; l++) {
            int f = tid + 256 * l;
            int ar = f >> 2;
            int ac = (f & 3) * 4;
            int grow = rowBase + ar;
            float4 av = make_float4(0.f, 0.f, 0.f, 0.f);
            if (grow < Nn) av = *(const float4*)&A[grow * K + kt + ac];
            if (BNA) {
                av.x = av.x * s_sc[kt + ac + 0] + s_sh[kt + ac + 0];
                av.y = av.y * s_sc[kt + ac + 1] + s_sh[kt + ac + 1];
                av.z = av.z * s_sc[kt + ac + 2] + s_sh[kt + ac + 2];
                av.w = av.w * s_sc[kt + ac + 3] + s_sh[kt + ac + 3];
            }
            Ast[buf][ac + 0][ar] = av.x;
            Ast[buf][ac + 1][ar] = av.y;
            Ast[buf][ac + 2][ar] = av.z;
            Ast[buf][ac + 3][ar] = av.w;
        }
#pragma unroll
        for (int l = 0; l < 2; l++) {
            int f = tid + 256 * l;
            int br = f >> 5;
            int p = f & 31;
            int c = (p < 16) ? (2 * p) : (2 * (p - 16) + 1);
            float4 bv = *(const float4*)&B[(kt + br) * NC + colBase + c * 4];
            *(float4*)&Bs[buf][br][p * 4] = bv;
        }
    };

    load_store(0, 0);
    __syncthreads();
    int cur = 0;

    for (int kt = 0; kt < K; kt += BK) {
        if (kt + BK < K) load_store(kt + BK, 1 - cur);  // overlaps with compute
#pragma unroll
        for (int kk = 0; kk < BK; kk++) {
            float4 a0 = *(const float4*)&Ast[cur][kk][ty * 8];
            float4 a1 = *(const float4*)&Ast[cur][kk][ty * 8 + 4];
            ulonglong2 bA = *(const ulonglong2*)&Bs[cur][kk][tx * 4];
            ulonglong2 bB = *(const ulonglong2*)&Bs[cur][kk][64 + tx * 4];
            float a8[8] = {a0.x, a0.y, a0.z, a0.w, a1.x, a1.y, a1.z, a1.w};
            unsigned long long bb[4] = {bA.x, bA.y, bB.x, bB.y};
            unsigned long long ap[8];
#pragma unroll
            for (int i = 0; i < 8; i++) ap[i] = pack2(a8[i]);
#pragma unroll
            for (int i = 0; i < 8; i++)
#pragma unroll
                for (int j = 0; j < 4; j++) fma2(acc[i][j], ap[i], bb[j]);
        }
        __syncthreads();
        cur ^= 1;
    }

    // ---------------- epilogue ----------------
    if (STATS) {
        for (int c = tid; c < SSZ; c += 256) {
            s_cs[c] = 0.f;
            s_cq[c] = 0.f;
        }
        __syncthreads();
    }

    int col = colBase + tx * 8;
    float b8[8] = {0.f, 0.f, 0.f, 0.f, 0.f, 0.f, 0.f, 0.f};
    if (BIAS) {
        float4 ba = *(const float4*)&bias[col];
        float4 bb = *(const float4*)&bias[col + 4];
        b8[0] = ba.x; b8[1] = ba.y; b8[2] = ba.z; b8[3] = ba.w;
        b8[4] = bb.x; b8[5] = bb.y; b8[6] = bb.z; b8[7] = bb.w;
    }
    float scR[8], shR[8];
    if (BNRES) {
#pragma unroll
        for (int j = 0; j < 8; j++) {
            scR[j] = s_sc[col + j];
            shR[j] = s_sh[col + j];
        }
    }

    float ps[8] = {0.f, 0.f, 0.f, 0.f, 0.f, 0.f, 0.f, 0.f};
    float qs[8] = {0.f, 0.f, 0.f, 0.f, 0.f, 0.f, 0.f, 0.f};

#pragma unroll
    for (int i = 0; i < 8; i++) {
        int row = rowBase + ty * 8 + i;
        if (row >= Nn) continue;
        float r8[8] = {0.f, 0.f, 0.f, 0.f, 0.f, 0.f, 0.f, 0.f};
        if (RES) {
            float4 ra = *(const float4*)&res[row * NC + col];
            float4 rb = *(const float4*)&res[row * NC + col + 4];
            r8[0] = ra.x; r8[1] = ra.y; r8[2] = ra.z; r8[3] = ra.w;
            r8[4] = rb.x; r8[5] = rb.y; r8[6] = rb.z; r8[7] = rb.w;
            if (BNRES) {
#pragma unroll
                for (int j = 0; j < 8; j++) r8[j] = r8[j] * scR[j] + shR[j];
            }
        }
        float o[8];
#pragma unroll
        for (int j = 0; j < 4; j++) {
            float2 p = *(float2*)&acc[i][j];
            o[2 * j] = p.x;
            o[2 * j + 1] = p.y;
        }
#pragma unroll
        for (int j = 0; j < 8; j++) {
            float vv = o[j];
            if (BIAS) vv += b8[j];
            if (RES) vv += r8[j];
            if (RELU) vv = vv > 0.f ? vv : 0.f;
            o[j] = vv;
            if (STATS) {
                ps[j] += vv;
                qs[j] += vv * vv;
            }
        }
        *(float4*)&C[row * NC + col] = make_float4(o[0], o[1], o[2], o[3]);
        *(float4*)&C[row * NC + col + 4] = make_float4(o[4], o[5], o[6], o[7]);
    }

    if (STATS) {
#pragma unroll
        for (int j = 0; j < 8; j++) {
            atomicAdd(&s_cs[tx * 8 + j], ps[j]);
            atomicAdd(&s_cq[tx * 8 + j], qs[j]);
        }
        __syncthreads();
        for (int c = tid; c < SSZ; c += 256) {
            atomicAdd(&stsum[colBase + c], (double)s_cs[c]);
            atomicAdd(&stsq[colBase + c], (double)s_cq[c]);
        }
    }
}

// ---------------- fused edge attention: one warp per dst node ----------------
__global__ void attn_fused_kernel() {
    int warp = blockIdx.x * (blockDim.x >> 5) + (threadIdx.x >> 5);
    int lane = threadIdx.x & 31;
    if (warp >= Nn) return;
    int dst = warp;

    float4 q4 = *(const float4*)&g_q[dst * Dd + lane * 4];

    float m = -INFINITY;
    float l = 0.0f;
    float4 acc = make_float4(0.f, 0.f, 0.f, 0.f);

    int beg = g_rowptr[dst];
    int end = g_rowptr[dst + 1];
    for (int j = beg; j < end; j++) {
        int src = g_col[j];
        float4 k4 = *(const float4*)&g_k[src * Dd + lane * 4];
        float p = q4.x * k4.x + q4.y * k4.y + q4.z * k4.z + q4.w * k4.w;
        p += __shfl_xor_sync(0xffffffffu, p, 1);
        p += __shfl_xor_sync(0xffffffffu, p, 2);
        float s = p * 0.25f;

        float newm = fmaxf(m, s);
        float corr = __expf(m - newm);
        float pe = __expf(s - newm);
        float4 v4 = *(const float4*)&g_v[src * Dd + lane * 4];
        acc.x = acc.x * corr + pe * v4.x;
        acc.y = acc.y * corr + pe * v4.y;
        acc.z = acc.z * corr + pe * v4.z;
        acc.w = acc.w * corr + pe * v4.w;
        l = l * corr + pe;
        m = newm;
    }
    float inv = (l > 0.f) ? (1.0f / l) : 0.0f;
    acc.x *= inv; acc.y *= inv; acc.z *= inv; acc.w *= inv;
    *(float4*)&g_attn[dst * Dd + lane * 4] = acc;
}

// ---------------- final projection (with fused BN on input) ----------------
__global__ void proj_kernel(const float* __restrict__ Wp, const float* __restrict__ bp,
                            const float* __restrict__ bng, const float* __restrict__ bnb,
                            float* __restrict__ out) {
    int warp = blockIdx.x * (blockDim.x >> 5) + (threadIdx.x >> 5);
    int lane = threadIdx.x & 31;
    if (warp >= Nn) return;

    float sc[4], sh[4];
#pragma unroll
    for (int i = 0; i < 4; i++) {
        int c = lane + 32 * i;
        double m = g_sum2[c] / (double)Nn;
        double var = g_sq2[c] / (double)Nn - m * m;
        float s = rsqrtf((float)var + EPSf) * bng[c];
        sc[i] = s;
        sh[i] = bnb[c] - (float)m * s;
    }

    float acc[Cc] = {0.f, 0.f, 0.f, 0.f, 0.f};
#pragma unroll
    for (int i = 0; i < 4; i++) {
        int k = lane + 32 * i;
        float xv = g_tmp2[warp * Dd + k] * sc[i] + sh[i];
#pragma unroll
        for (int c = 0; c < Cc; c++) acc[c] += xv * Wp[k * Cc + c];
    }
#pragma unroll
    for (int c = 0; c < Cc; c++) {
#pragma unroll
        for (int o = 16; o > 0; o >>= 1) acc[c] += __shfl_down_sync(0xffffffffu, acc[c], o);
    }
    if (lane == 0) {
#pragma unroll
        for (int c = 0; c < Cc; c++) out[warp * Cc + c] = acc[c] + bp[c];
    }
}

// ---------------- launch ----------------
extern "C" void kernel_launch(void* const* d_in, const int* in_sizes, int n_in,
                              void* d_out, int out_size) {
    const float* x   = (const float*)d_in[0];
    const int*   ei  = (const int*)d_in[1];
    const float* Wq  = (const float*)d_in[2];
    const float* Wk  = (const float*)d_in[3];
    const float* Wv  = (const float*)d_in[4];
    const float* Wo  = (const float*)d_in[5];
    const float* g1  = (const float*)d_in[6];
    const float* bn1 = (const float*)d_in[7];
    const float* W1  = (const float*)d_in[8];
    const float* bf1 = (const float*)d_in[9];
    const float* W2  = (const float*)d_in[10];
    const float* bf2 = (const float*)d_in[11];
    const float* g2  = (const float*)d_in[12];
    const float* bn2 = (const float*)d_in[13];
    const float* Wp  = (const float*)d_in[14];
    const float* bp  = (const float*)d_in[15];
    float* out = (float*)d_out;

    float *pq, *pk, *pv, *pattn, *ptmp1, *ptmp2, *pff;
    double *psum1, *psq1, *psum2, *psq2;
    cudaGetSymbolAddress((void**)&pq, g_q);
    cudaGetSymbolAddress((void**)&pk, g_k);
    cudaGetSymbolAddress((void**)&pv, g_v);
    cudaGetSymbolAddress((void**)&pattn, g_attn);
    cudaGetSymbolAddress((void**)&ptmp1, g_tmp1);
    cudaGetSymbolAddress((void**)&ptmp2, g_tmp2);
    cudaGetSymbolAddress((void**)&pff, g_ff);
    cudaGetSymbolAddress((void**)&psum1, g_sum1);
    cudaGetSymbolAddress((void**)&psq1, g_sq1);
    cudaGetSymbolAddress((void**)&psum2, g_sum2);
    cudaGetSymbolAddress((void**)&psq2, g_sq2);

    const int gemmRows = (Nn + 127) / 128;  // 391
    const int edgeBlocks = (Ee + 255) / 256;
    const int nodeBlocks = (Nn + 255) / 256;
    const int warpBlocks = (Nn + 7) / 8;

    // #1..#3
    csr_zero_kernel<<<nodeBlocks, 256>>>();
    csr_hist_kernel<<<edgeBlocks, 256>>>(ei);
    csr_scan1_kernel<<<SCAN_NB, SCAN_B>>>();
    // #4: layer-0 QKV (profiled launch) — raw x input, no BN
    gemm_kernel<Dd, Dd, false, false, false, false, false, false, 3>
        <<<dim3(gemmRows, 3), 256>>>(x, Wq, Wk, Wv, nullptr, nullptr,
                                     nullptr, nullptr, nullptr, nullptr,
                                     nullptr, nullptr, pq, pk, pv);
    // #5, #6: finish CSR
    csr_scan23_kernel<<<SCAN_NB, SCAN_B>>>();
    csr_scatter_kernel<<<edgeBlocks, 256>>>(ei);

    for (int i = 0; i < Ll; i++) {
        const float* wq = Wq + (size_t)i * Dd * Dd;
        const float* wk = Wk + (size_t)i * Dd * Dd;
        const float* wv = Wv + (size_t)i * Dd * Dd;
        const float* wo = Wo + (size_t)i * Dd * Dd;
        const float* w1 = W1 + (size_t)i * Dd * FFd;
        const float* w2 = W2 + (size_t)i * FFd * Dd;

        if (i > 0) {
            // QKV with BN2(prev) applied to input tmp2
            gemm_kernel<Dd, Dd, false, false, false, true, false, false, 3>
                <<<dim3(gemmRows, 3), 256>>>(ptmp2, wq, wk, wv, nullptr, nullptr,
                                             g2 + (i - 1) * Dd, bn2 + (i - 1) * Dd,
                                             psum2, psq2, nullptr, nullptr,
                                             pq, pk, pv);
        }

        attn_fused_kernel<<<warpBlocks, 256>>>();

        zero_stats_kernel<<<1, 128>>>(psum1, psq1);

        if (i == 0) {
            // tmp1 = attn@Wo + x (raw residual), stats1 accumulated
            gemm_kernel<Dd, Dd, false, false, true, false, false, true, 1>
                <<<dim3(gemmRows, 1), 256>>>(pattn, wo, nullptr, nullptr,
                                             nullptr, x, nullptr, nullptr,
                                             nullptr, nullptr, psum1, psq1,
                                             ptmp1, nullptr, nullptr);
        } else {
            // tmp1 = attn@Wo + BN2(tmp2), stats1 accumulated
            gemm_kernel<Dd, Dd, false, false, true, false, true, true, 1>
                <<<dim3(gemmRows, 1), 256>>>(pattn, wo, nullptr, nullptr,
                                             nullptr, ptmp2,
                                             g2 + (i - 1) * Dd, bn2 + (i - 1) * Dd,
                                             psum2, psq2, psum1, psq1,
                                             ptmp1, nullptr, nullptr);
        }

        // ff = relu(BN1(tmp1)@W1 + bf1)
        gemm_kernel<Dd, FFd, true, true, false, true, false, false, 1>
            <<<dim3(gemmRows, 2), 256>>>(ptmp1, w1, nullptr, nullptr,
                                         bf1 + i * FFd, nullptr,
                                         g1 + i * Dd, bn1 + i * Dd,
                                         psum1, psq1, nullptr, nullptr,
                                         pff, nullptr, nullptr);

        zero_stats_kernel<<<1, 128>>>(psum2, psq2);

        // tmp2 = ff@W2 + bf2 + BN1(tmp1), stats2 accumulated
        gemm_kernel<FFd, Dd, true, false, true, false, true, true, 1>
            <<<dim3(gemmRows, 1), 256>>>(pff, w2, nullptr, nullptr,
                                         bf2 + i * Dd, ptmp1,
                                         g1 + i * Dd, bn1 + i * Dd,
                                         psum1, psq1, psum2, psq2,
                                         ptmp2, nullptr, nullptr);
    }

    // node_pred = BN2(tmp2) @ Wp + bp
    proj_kernel<<<warpBlocks, 256>>>(Wp, bp, g2 + (Ll - 1) * Dd, bn2 + (Ll - 1) * Dd, out);
}